// round 6
// baseline (speedup 1.0000x reference)
#include <cuda_runtime.h>
#include <cuda_bf16.h>
#include <cstdint>

// Problem shapes (fixed by reference setup_inputs)
#define N_SEQ   256
#define M_GENES 2000
#define D_DIM   128

// Fused kernel: register-resident normalized rows (R5 structure) + SMEM
// transpose + cp.async.bulk 4KB contiguous stores.
//
//   Block: 256 threads = 8 warps. Warp w owns gene m = blockIdx.x*8 + w.
//   n-slab: 64 positions per block (blockIdx.y in 0..3).
//
//   The 64 n-rows are processed as 16 tiles of 4 n. For each tile the 8
//   warps deposit their selected rows into a 16KB SMEM buffer laid out as
//   [n][m][d] (exactly the output order), then one elected thread issues
//   four 4KB bulk async stores (one per n-row, contiguous across the
//   block's 8 genes). Double buffering (wait_group.read 1) overlaps the
//   async drain with the next tile's fill.
//
//   Why: direct per-warp STG streams advance 512B at a time with 1MB
//   strides -> one DRAM row activation per 512B written. 4KB in-order
//   bursts amortize ACT/PRE over full rows, raising sustained write BW.
__global__ void __launch_bounds__(256) fused_gene_embed_kernel(
    const int* __restrict__ gene_seq,      // (N, M)
    const float* __restrict__ emb,         // (M, 4, D)
    float* __restrict__ out)               // (N, M, D)
{
    // [buffer][n_local][m_local(warp)][lane] : 2 x 16 KB
    __shared__ alignas(1024) float4 tile[2][4][8][32];

    const int tid  = threadIdx.x;
    const int warp = tid >> 5;
    const int lane = tid & 31;
    const int m0 = blockIdx.x * 8;          // grid.x = 250 (exact)
    const int m  = m0 + warp;
    const int n0 = blockIdx.y * 64;         // grid.y = 4   (exact)

    // ---- per-lane sequence indices for the two 32-row halves ----
    const int glA = gene_seq[(size_t)(n0 + lane)      * M_GENES + m];
    const int glB = gene_seq[(size_t)(n0 + 32 + lane) * M_GENES + m];

    // ---- load + normalize this gene's 4 table rows in registers ----
    const float4* src = reinterpret_cast<const float4*>(emb) + (size_t)m * 4 * 32;
    float4 r0 = src[lane];
    float4 r1 = src[32 + lane];
    float4 r2 = src[64 + lane];
    float4 r3 = src[96 + lane];
    {
        float s0 = r0.x*r0.x + r0.y*r0.y + r0.z*r0.z + r0.w*r0.w;
        float s1 = r1.x*r1.x + r1.y*r1.y + r1.z*r1.z + r1.w*r1.w;
        float s2 = r2.x*r2.x + r2.y*r2.y + r2.z*r2.z + r2.w*r2.w;
        float s3 = r3.x*r3.x + r3.y*r3.y + r3.z*r3.z + r3.w*r3.w;
        #pragma unroll
        for (int off = 16; off > 0; off >>= 1) {
            s0 += __shfl_xor_sync(0xFFFFFFFFu, s0, off);
            s1 += __shfl_xor_sync(0xFFFFFFFFu, s1, off);
            s2 += __shfl_xor_sync(0xFFFFFFFFu, s2, off);
            s3 += __shfl_xor_sync(0xFFFFFFFFu, s3, off);
        }
        const float i0 = 1.0f / fmaxf(sqrtf(s0), 1e-12f);
        const float i1 = 1.0f / fmaxf(sqrtf(s1), 1e-12f);
        const float i2 = 1.0f / fmaxf(sqrtf(s2), 1e-12f);
        const float i3 = 1.0f / fmaxf(sqrtf(s3), 1e-12f);
        r0.x *= i0; r0.y *= i0; r0.z *= i0; r0.w *= i0;
        r1.x *= i1; r1.y *= i1; r1.z *= i1; r1.w *= i1;
        r2.x *= i2; r2.y *= i2; r2.z *= i2; r2.w *= i2;
        r3.x *= i3; r3.y *= i3; r3.z *= i3; r3.w *= i3;
    }

    char* const obase = reinterpret_cast<char*>(out);

    #pragma unroll
    for (int t = 0; t < 16; t++) {
        const int buf = t & 1;

        // Before refilling this buffer, ensure the bulk store issued on it
        // two tiles ago has finished reading SMEM (allow 1 group in flight).
        if (t >= 2) {
            if (tid == 0)
                asm volatile("cp.async.bulk.wait_group.read 1;" ::: "memory");
            __syncthreads();
        }

        // Fill: each warp writes its 4 selected rows (STS.128, conflict-free).
        #pragma unroll
        for (int i = 0; i < 4; i++) {
            const int nn = t * 4 + i;                       // 0..63, compile-time
            const int g = (nn < 32) ? __shfl_sync(0xFFFFFFFFu, glA, nn)
                                    : __shfl_sync(0xFFFFFFFFu, glB, nn - 32);
            const float4 v = (g == 0) ? r0 : (g == 1) ? r1 : (g == 2) ? r2 : r3;
            tile[buf][i][warp][lane] = v;
        }
        __syncthreads();

        // Drain: four 4KB contiguous bulk stores (one per n-row).
        if (tid == 0) {
            asm volatile("fence.proxy.async.shared::cta;" ::: "memory");
            #pragma unroll
            for (int i = 0; i < 4; i++) {
                const int n = n0 + t * 4 + i;
                char* dst = obase + ((size_t)n * M_GENES + m0) * 512;
                uint32_t saddr = (uint32_t)__cvta_generic_to_shared(&tile[buf][i][0][0]);
                asm volatile(
                    "cp.async.bulk.global.shared::cta.bulk_group [%0], [%1], %2;"
                    :: "l"(dst), "r"(saddr), "r"(4096) : "memory");
            }
            asm volatile("cp.async.bulk.commit_group;" ::: "memory");
        }
    }

    // Drain all outstanding bulk stores before kernel exit.
    if (tid == 0)
        asm volatile("cp.async.bulk.wait_group 0;" ::: "memory");
}

extern "C" void kernel_launch(void* const* d_in, const int* in_sizes, int n_in,
                              void* d_out, int out_size) {
    const int* gene_seq = (const int*)d_in[0];      // (256, 2000) int32
    const float* emb    = (const float*)d_in[1];    // (2000, 4, 128) fp32
    float* out          = (float*)d_out;            // (256, 2000, 128) fp32

    dim3 grid(M_GENES / 8, N_SEQ / 64, 1);          // (250, 4)
    fused_gene_embed_kernel<<<grid, 256>>>(gene_seq, emb, out);
}

// round 7
// speedup vs baseline: 1.0447x; 1.0447x over previous
#include <cuda_runtime.h>
#include <cuda_bf16.h>
#include <cstdint>

// Problem shapes (fixed by reference setup_inputs)
#define N_SEQ   256
#define M_GENES 2000
#define D_DIM   128

// Fused kernel, register-resident rows, 2 n-tiles per warp (R5 structure),
// default write-back stores.
//
//   Block: 256 threads = 8 warps. Warp w owns gene m = blockIdx.x*8 + w.
//   Tile:  2 x 32 sequence positions (blockIdx.y selects a 64-row slab).
//
//   Key change vs R5: stores are plain write-back (no .cs evict-first).
//   The output buffer (262 MB) is rewritten every graph replay; with
//   write-back allocation the ~126 MB L2 retains the tail of the write
//   stream across iterations, so those lines are rewritten with L2 hits
//   and never drain to DRAM — cutting steady-state HBM write traffic well
//   below the full 262 MB that .cs was forcing out every pass.
__global__ void __launch_bounds__(256) fused_gene_embed_kernel(
    const int* __restrict__ gene_seq,      // (N, M)
    const float* __restrict__ emb,         // (M, 4, D)
    float* __restrict__ out)               // (N, M, D)
{
    const int warp = threadIdx.x >> 5;
    const int lane = threadIdx.x & 31;
    const int m  = blockIdx.x * 8 + warp;   // grid.x = 250 (exact)
    const int n0 = blockIdx.y * 64;         // grid.y = 4   (exact)

    // ---- per-lane sequence indices for the two 32-row tiles ----
    const int glA = gene_seq[(size_t)(n0 + lane)      * M_GENES + m];
    const int glB = gene_seq[(size_t)(n0 + 32 + lane) * M_GENES + m];

    // ---- load this gene's 4 table rows into registers ----
    const float4* src = reinterpret_cast<const float4*>(emb) + (size_t)m * 4 * 32;
    float4 r0 = src[lane];
    float4 r1 = src[32 + lane];
    float4 r2 = src[64 + lane];
    float4 r3 = src[96 + lane];

    // ---- normalize rows in registers (butterfly keeps norm in all lanes) ----
    {
        float s0 = r0.x*r0.x + r0.y*r0.y + r0.z*r0.z + r0.w*r0.w;
        float s1 = r1.x*r1.x + r1.y*r1.y + r1.z*r1.z + r1.w*r1.w;
        float s2 = r2.x*r2.x + r2.y*r2.y + r2.z*r2.z + r2.w*r2.w;
        float s3 = r3.x*r3.x + r3.y*r3.y + r3.z*r3.z + r3.w*r3.w;
        #pragma unroll
        for (int off = 16; off > 0; off >>= 1) {
            s0 += __shfl_xor_sync(0xFFFFFFFFu, s0, off);
            s1 += __shfl_xor_sync(0xFFFFFFFFu, s1, off);
            s2 += __shfl_xor_sync(0xFFFFFFFFu, s2, off);
            s3 += __shfl_xor_sync(0xFFFFFFFFu, s3, off);
        }
        const float i0 = 1.0f / fmaxf(sqrtf(s0), 1e-12f);
        const float i1 = 1.0f / fmaxf(sqrtf(s1), 1e-12f);
        const float i2 = 1.0f / fmaxf(sqrtf(s2), 1e-12f);
        const float i3 = 1.0f / fmaxf(sqrtf(s3), 1e-12f);
        r0.x *= i0; r0.y *= i0; r0.z *= i0; r0.w *= i0;
        r1.x *= i1; r1.y *= i1; r1.z *= i1; r1.w *= i1;
        r2.x *= i2; r2.y *= i2; r2.z *= i2; r2.w *= i2;
        r3.x *= i3; r3.y *= i3; r3.z *= i3; r3.w *= i3;
    }

    // ---- two interleaved write-back store chains ----
    const size_t row_stride = (size_t)M_GENES * 32;   // one n step (float4 units)
    float4* obA = reinterpret_cast<float4*>(out)
                + ((size_t)n0 * M_GENES + m) * 32 + lane;
    float4* obB = obA + row_stride * 32;

    #pragma unroll 8
    for (int nn = 0; nn < 32; nn++) {
        const int gA = __shfl_sync(0xFFFFFFFFu, glA, nn);
        const int gB = __shfl_sync(0xFFFFFFFFu, glB, nn);
        const float4 vA = (gA == 0) ? r0 : (gA == 1) ? r1 : (gA == 2) ? r2 : r3;
        const float4 vB = (gB == 0) ? r0 : (gB == 1) ? r1 : (gB == 2) ? r2 : r3;
        *obA = vA;          // default write-back: allocate in L2, stay dirty
        *obB = vB;
        obA += row_stride;
        obB += row_stride;
    }
}

extern "C" void kernel_launch(void* const* d_in, const int* in_sizes, int n_in,
                              void* d_out, int out_size) {
    const int* gene_seq = (const int*)d_in[0];      // (256, 2000) int32
    const float* emb    = (const float*)d_in[1];    // (2000, 4, 128) fp32
    float* out          = (float*)d_out;            // (256, 2000, 128) fp32

    dim3 grid(M_GENES / 8, N_SEQ / 64, 1);          // (250, 4)
    fused_gene_embed_kernel<<<grid, 256>>>(gene_seq, emb, out);
}